// round 4
// baseline (speedup 1.0000x reference)
#include <cuda_runtime.h>
#include <math.h>

#define BB   64
#define SS   2048
#define DD   1024
#define HH   300
#define OO   2
#define SCH  16                 // s-chunks for the big reduction
#define SPC  (SS / SCH)         // 128 s per chunk
#define D4   (DD / 4)           // 256 float4 per row

// Scratch (allocation-free rule: __device__ globals)
__device__ int   g_end[BB];
__device__ float g_partial[BB][SCH][DD];
__device__ float g_euph[BB][DD];
__device__ float g_hidden[BB][HH];

// ---------------------------------------------------------------------------
// 1) big masked segment-sum with fused end-index scan.
//    partial[b][c][d] = sum over s in chunk c (s<end, mask!=0) of x[b][s][d]*m.
//    Each block re-derives end from the 8KB ids row (L2-cached across the 16
//    chunk-blocks of the same b) — saves a separate launch + serialization.
// ---------------------------------------------------------------------------
__global__ __launch_bounds__(256) void k_reduce(const float* __restrict__ x,
                                                const float* __restrict__ mask,
                                                const int*   __restrict__ ids) {
    int b = blockIdx.x;
    int c = blockIdx.y;
    int t = threadIdx.x;

    __shared__ int   s_end;
    __shared__ float sm[SPC];
    if (t == 0) s_end = 0x7fffffff;
    __syncthreads();

    // end = first s with ids[b][s] == 1, fallback B (reference's except-path)
    const int* row = ids + b * SS;
#pragma unroll
    for (int i = 0; i < SS / 256; i++) {
        int s = t + i * 256;
        if (row[s] == 1) atomicMin(&s_end, s);
    }
    __syncthreads();
    int end = (s_end == 0x7fffffff) ? BB : s_end;
    if (c == 0 && t == 0) g_end[b] = end;

    // stage mask for this chunk, folding s<end validity in
    int s0 = c * SPC;
    if (t < SPC) {
        int s = s0 + t;
        sm[t] = (s < end) ? mask[b * SS + s] : 0.0f;
    }
    __syncthreads();

    const float4* xp = (const float4*)(x + (long long)b * SS * DD) + t;

    float4 acc = make_float4(0.f, 0.f, 0.f, 0.f);
#pragma unroll 8
    for (int i = 0; i < SPC; i++) {
        float m = sm[i];
        if (m != 0.0f) {
            float4 v = xp[(long long)(s0 + i) * D4];
            acc.x += v.x * m;
            acc.y += v.y * m;
            acc.z += v.z * m;
            acc.w += v.w * m;
        }
    }
    ((float4*)g_partial[b][c])[t] = acc;
}

// ---------------------------------------------------------------------------
// 2) fold the SCH partials and divide by end:  euph[b][d]
// ---------------------------------------------------------------------------
__global__ __launch_bounds__(256) void k_combine() {
    int b = blockIdx.x;
    int t = threadIdx.x;
    float inv = 1.0f / (float)g_end[b];
    float4 acc = make_float4(0.f, 0.f, 0.f, 0.f);
#pragma unroll
    for (int c = 0; c < SCH; c++) {
        float4 v = ((const float4*)g_partial[b][c])[t];
        acc.x += v.x; acc.y += v.y; acc.z += v.z; acc.w += v.w;
    }
    acc.x *= inv; acc.y *= inv; acc.z *= inv; acc.w *= inv;
    ((float4*)g_euph[b])[t] = acc;
}

// ---------------------------------------------------------------------------
// 3) hidden = tanh(euph @ W1^T + b1).  Grid (4 bTiles, 75 hTiles), 4 warps.
//    Warp owns one h; its W1 row lives in REGISTERS (8 x float4 per lane) and
//    is reused across 16 batches -> W1 traffic 4.8MB, euph 19MB (L1/L2 hits),
//    vs 77MB before.
// ---------------------------------------------------------------------------
__global__ __launch_bounds__(128) void k_hidden(const float* __restrict__ W1,
                                                const float* __restrict__ b1) {
    int warp = threadIdx.x >> 5;
    int lane = threadIdx.x & 31;
    int h    = blockIdx.y * 4 + warp;          // 75*4 = 300, always valid
    int b0   = blockIdx.x * 16;                // 4*16  = 64

    const float4* w4p = (const float4*)(W1 + (long long)h * DD);
    float4 w[8];
#pragma unroll
    for (int i = 0; i < 8; i++) w[i] = w4p[lane + 32 * i];
    float bias = b1[h];

    for (int bi = 0; bi < 16; bi++) {
        const float4* e4 = (const float4*)g_euph[b0 + bi];
        float s = 0.f;
#pragma unroll
        for (int i = 0; i < 8; i++) {
            float4 e = e4[lane + 32 * i];
            s += e.x * w[i].x + e.y * w[i].y + e.z * w[i].z + e.w * w[i].w;
        }
#pragma unroll
        for (int off = 16; off > 0; off >>= 1)
            s += __shfl_xor_sync(0xffffffffu, s, off);
        if (lane == 0)
            g_hidden[b0 + bi][h] = tanhf(s + bias);
    }
}

// ---------------------------------------------------------------------------
// 4) out = hidden @ W2^T + b2.  Grid B, 2 warps/block, one warp per output.
// ---------------------------------------------------------------------------
__global__ __launch_bounds__(64) void k_out(const float* __restrict__ W2,
                                            const float* __restrict__ b2,
                                            float* __restrict__ out) {
    int b    = blockIdx.x;
    int warp = threadIdx.x >> 5;               // 0..1
    int lane = threadIdx.x & 31;

    const float* hid = g_hidden[b];
    const float* w   = W2 + warp * HH;
    float s = 0.f;
    for (int k = lane; k < HH; k += 32)
        s += hid[k] * w[k];
#pragma unroll
    for (int off = 16; off > 0; off >>= 1)
        s += __shfl_xor_sync(0xffffffffu, s, off);
    if (lane == 0)
        out[b * OO + warp] = s + b2[warp];
}

// ---------------------------------------------------------------------------
extern "C" void kernel_launch(void* const* d_in, const int* in_sizes, int n_in,
                              void* d_out, int out_size) {
    const float* x    = (const float*)d_in[0];       // [B,S,D] f32
    const int*   ids  = (const int*)d_in[1];         // [B,S]   i32 (JAX x64 off)
    const float* mask = (const float*)d_in[2];       // [B,S,1] f32
    const float* W1   = (const float*)d_in[3];       // [H,D]
    const float* b1   = (const float*)d_in[4];       // [H]
    const float* W2   = (const float*)d_in[5];       // [OUT,H]
    const float* b2   = (const float*)d_in[6];       // [OUT]
    float*       out  = (float*)d_out;               // [B,OUT]

    k_reduce <<<dim3(BB, SCH), 256>>>(x, mask, ids);
    k_combine<<<BB, 256>>>();
    k_hidden <<<dim3(4, HH / 4), 128>>>(W1, b1);
    k_out    <<<BB, 64>>>(W2, b2, out);
}

// round 5
// speedup vs baseline: 1.1859x; 1.1859x over previous
#include <cuda_runtime.h>
#include <math.h>

#define BB   64
#define SS   2048
#define DD   1024
#define HH   300
#define OO   2
#define SCH  16                 // s-chunks for the big reduction
#define SPC  (SS / SCH)         // 128 s per chunk
#define D4   (DD / 4)           // 256 float4 per row

// Scratch (allocation-free rule: __device__ globals)
__device__ int   g_end[BB];
__device__ float g_partial[BB][SCH][DD];
__device__ float g_euph[BB][DD];
__device__ float g_hidden[BB][HH];

// ---------------------------------------------------------------------------
// 1) first index where input_ids[b,s]==1; fallback = B (reference's
//    except-path quirk). Separate tiny launch — keeping this OUT of the
//    bandwidth kernel (R4 fusion regressed 15us).
// ---------------------------------------------------------------------------
__global__ void k_end(const int* __restrict__ ids) {
    int b = blockIdx.x;
    __shared__ int m;
    if (threadIdx.x == 0) m = 0x7fffffff;
    __syncthreads();
    const int* row = ids + b * SS;
    for (int s = threadIdx.x; s < SS; s += blockDim.x)
        if (row[s] == 1) atomicMin(&m, s);
    __syncthreads();
    if (threadIdx.x == 0) g_end[b] = (m == 0x7fffffff) ? BB : m;
}

// ---------------------------------------------------------------------------
// 2) big masked segment-sum with COMPACTED row list: stage (s, m) pairs with
//    m!=0 && s<end into smem (order-free; sum is order-insensitive within fp
//    tolerance), then run an unconditional 4-way-unrolled float4 stream.
//    All 256 threads read the same s per iter -> fully coalesced rows.
// ---------------------------------------------------------------------------
__global__ __launch_bounds__(256) void k_reduce(const float* __restrict__ x,
                                                const float* __restrict__ mask) {
    int b = blockIdx.x;
    int c = blockIdx.y;
    int t = threadIdx.x;
    int end = g_end[b];
    int s0  = c * SPC;

    __shared__ float s_m[SPC];
    __shared__ int   s_idx[SPC];
    __shared__ int   s_cnt;
    if (t == 0) s_cnt = 0;
    __syncthreads();

    if (t < SPC) {                          // first 128 threads stage+compact
        int s = s0 + t;
        float m = (s < end) ? mask[b * SS + s] : 0.0f;
        if (m != 0.0f) {
            int p = atomicAdd(&s_cnt, 1);
            s_idx[p] = t;
            s_m[p]   = m;
        }
    }
    __syncthreads();
    int n = s_cnt;

    const float4* xp = (const float4*)(x + (long long)b * SS * DD)
                       + (long long)s0 * D4 + t;

    float4 acc = make_float4(0.f, 0.f, 0.f, 0.f);
    int i = 0;
    for (; i + 4 <= n; i += 4) {
        int   j0 = s_idx[i],     j1 = s_idx[i + 1];
        int   j2 = s_idx[i + 2], j3 = s_idx[i + 3];
        float m0 = s_m[i],       m1 = s_m[i + 1];
        float m2 = s_m[i + 2],   m3 = s_m[i + 3];
        float4 v0 = xp[j0 * D4];
        float4 v1 = xp[j1 * D4];
        float4 v2 = xp[j2 * D4];
        float4 v3 = xp[j3 * D4];
        acc.x += v0.x * m0; acc.y += v0.y * m0; acc.z += v0.z * m0; acc.w += v0.w * m0;
        acc.x += v1.x * m1; acc.y += v1.y * m1; acc.z += v1.z * m1; acc.w += v1.w * m1;
        acc.x += v2.x * m2; acc.y += v2.y * m2; acc.z += v2.z * m2; acc.w += v2.w * m2;
        acc.x += v3.x * m3; acc.y += v3.y * m3; acc.z += v3.z * m3; acc.w += v3.w * m3;
    }
    for (; i < n; i++) {
        int   j = s_idx[i];
        float m = s_m[i];
        float4 v = xp[j * D4];
        acc.x += v.x * m; acc.y += v.y * m; acc.z += v.z * m; acc.w += v.w * m;
    }
    ((float4*)g_partial[b][c])[t] = acc;
}

// ---------------------------------------------------------------------------
// 3) fold the SCH partials and divide by end:  euph[b][d]
// ---------------------------------------------------------------------------
__global__ __launch_bounds__(256) void k_combine() {
    int b = blockIdx.x;
    int t = threadIdx.x;
    float inv = 1.0f / (float)g_end[b];
    float4 acc = make_float4(0.f, 0.f, 0.f, 0.f);
#pragma unroll
    for (int c = 0; c < SCH; c++) {
        float4 v = ((const float4*)g_partial[b][c])[t];
        acc.x += v.x; acc.y += v.y; acc.z += v.z; acc.w += v.w;
    }
    acc.x *= inv; acc.y *= inv; acc.z *= inv; acc.w *= inv;
    ((float4*)g_euph[b])[t] = acc;
}

// ---------------------------------------------------------------------------
// 4) hidden = tanh(euph @ W1^T + b1).  Grid (4 bTiles, 75 hTiles), 4 warps.
//    Warp owns one h; W1 row held in registers, reused across 16 batches.
// ---------------------------------------------------------------------------
__global__ __launch_bounds__(128) void k_hidden(const float* __restrict__ W1,
                                                const float* __restrict__ b1) {
    int warp = threadIdx.x >> 5;
    int lane = threadIdx.x & 31;
    int h    = blockIdx.y * 4 + warp;          // 75*4 = 300, always valid
    int b0   = blockIdx.x * 16;                // 4*16  = 64

    const float4* w4p = (const float4*)(W1 + (long long)h * DD);
    float4 w[8];
#pragma unroll
    for (int i = 0; i < 8; i++) w[i] = w4p[lane + 32 * i];
    float bias = b1[h];

    for (int bi = 0; bi < 16; bi++) {
        const float4* e4 = (const float4*)g_euph[b0 + bi];
        float s = 0.f;
#pragma unroll
        for (int i = 0; i < 8; i++) {
            float4 e = e4[lane + 32 * i];
            s += e.x * w[i].x + e.y * w[i].y + e.z * w[i].z + e.w * w[i].w;
        }
#pragma unroll
        for (int off = 16; off > 0; off >>= 1)
            s += __shfl_xor_sync(0xffffffffu, s, off);
        if (lane == 0)
            g_hidden[b0 + bi][h] = tanhf(s + bias);
    }
}

// ---------------------------------------------------------------------------
// 5) out = hidden @ W2^T + b2.  Grid B, 2 warps/block, one warp per output.
// ---------------------------------------------------------------------------
__global__ __launch_bounds__(64) void k_out(const float* __restrict__ W2,
                                            const float* __restrict__ b2,
                                            float* __restrict__ out) {
    int b    = blockIdx.x;
    int warp = threadIdx.x >> 5;               // 0..1
    int lane = threadIdx.x & 31;

    const float* hid = g_hidden[b];
    const float* w   = W2 + warp * HH;
    float s = 0.f;
    for (int k = lane; k < HH; k += 32)
        s += hid[k] * w[k];
#pragma unroll
    for (int off = 16; off > 0; off >>= 1)
        s += __shfl_xor_sync(0xffffffffu, s, off);
    if (lane == 0)
        out[b * OO + warp] = s + b2[warp];
}

// ---------------------------------------------------------------------------
extern "C" void kernel_launch(void* const* d_in, const int* in_sizes, int n_in,
                              void* d_out, int out_size) {
    const float* x    = (const float*)d_in[0];       // [B,S,D] f32
    const int*   ids  = (const int*)d_in[1];         // [B,S]   i32 (JAX x64 off)
    const float* mask = (const float*)d_in[2];       // [B,S,1] f32
    const float* W1   = (const float*)d_in[3];       // [H,D]
    const float* b1   = (const float*)d_in[4];       // [H]
    const float* W2   = (const float*)d_in[5];       // [OUT,H]
    const float* b2   = (const float*)d_in[6];       // [OUT]
    float*       out  = (float*)d_out;               // [B,OUT]

    k_end    <<<BB, 256>>>(ids);
    k_reduce <<<dim3(BB, SCH), 256>>>(x, mask);
    k_combine<<<BB, 256>>>();
    k_hidden <<<dim3(4, HH / 4), 128>>>(W1, b1);
    k_out    <<<BB, 64>>>(W2, b2, out);
}